// round 11
// baseline (speedup 1.0000x reference)
#include <cuda_runtime.h>
#include <cstdint>

#define BATCH 4
#define NPTS  8192
#define GDIM  64                  // grid cells per axis
#define NCELL (GDIM * GDIM)       // 4096
#define CAP   20                  // max pts/cell (lambda=2; P(overflow)~1e-14)
#define HCELL (1.0f / GDIM)
#define NTAB  (2 * BATCH)         // set s (0=pred,1=gt) x batch
#define NQ    (2 * BATCH * NPTS)  // 65536 points == queries
#define NTHR  256
#define NBLK  (NQ / NTHR)         // 256 blocks (all co-resident: 148 SMs)

// Persistent scratch. g_ccnt zero at load; last block re-zeros it each call.
__device__ int      g_ccnt[NTAB * NCELL];
__device__ float2   g_cell[NTAB * NCELL * CAP];    // 5.2 MB (L2-resident)
__device__ float    g_part[NBLK];
__device__ unsigned g_count, g_sense, g_done;      // barrier + last-block state

__device__ __forceinline__ unsigned ld_acq(const unsigned* p) {
    unsigned v;
    asm volatile("ld.acquire.gpu.u32 %0, [%1];" : "=r"(v) : "l"(p) : "memory");
    return v;
}

// Sense-reversing grid barrier. Safe: all NBLK blocks are co-resident
// (256 blocks << capacity at 256 thr / ~48 regs / 1KB smem per block).
// gen is read BEFORE this block's arrive, so it always predates the release.
__device__ __forceinline__ void grid_barrier() {
    __syncthreads();
    if (threadIdx.x == 0) {
        unsigned gen = ld_acq(&g_sense);
        __threadfence();                                  // release fill stores
        if (atomicAdd(&g_count, 1u) == NBLK - 1) {
            g_count = 0;
            __threadfence();
            atomicAdd(&g_sense, 1u);                      // release
        } else {
            while (ld_acq(&g_sense) == gen) __nanosleep(64);
        }
    }
    __syncthreads();
}

__device__ __forceinline__ void scan_cell(const int* __restrict__ cnts,
                                          const float2* __restrict__ cells,
                                          int c, float qx, float qy, float& best) {
    int n = min(cnts[c], CAP);
    const float2* p = &cells[(size_t)c * CAP];
    for (int j = 0; j < n; j++) {
        float2 t = p[j];
        float dx = qx - t.x, dy = qy - t.y;
        best = fminf(best, fmaf(dx, dx, dy * dy));
    }
}

// ============================================================================
// One persistent kernel: fill -> grid barrier -> search -> last-block final.
// Thread gid owns point (s,b,i): bins it (phase 1) and uses it as the query
// against the OTHER set (phase 2). Exact NN: 3x3 fast path (prefetched
// counts) + expanding Chebyshev rings with lower-bound termination; result
// depends only on candidate sets -> deterministic under atomic fill order.
// Final sum is fixed-order trees -> deterministic regardless of last block.
// ============================================================================
__global__ __launch_bounds__(NTHR) void chamfer_all(const float2* __restrict__ pred,
                                                    const float2* __restrict__ gt,
                                                    float* __restrict__ out) {
    const int t = threadIdx.x, bid = blockIdx.x;
    const int gid = bid * NTHR + t;
    const int s = gid >> 15, b = (gid >> 13) & 3, i = gid & (NPTS - 1);

    // ---- Phase 1: bin own point (this is also our query) ----
    const float2* src = s ? gt : pred;
    const float2 q = src[b * NPTS + i];
    const int cx = min(GDIM - 1, max(0, (int)(q.x * (float)GDIM)));
    const int cy = min(GDIM - 1, max(0, (int)(q.y * (float)GDIM)));
    {
        int cell = (s * BATCH + b) * NCELL + cy * GDIM + cx;
        int pos = atomicAdd(&g_ccnt[cell], 1);
        if (pos < CAP) g_cell[cell * CAP + pos] = q;
    }

    grid_barrier();

    // ---- Phase 2: exact NN against the other set ----
    const int o = s ^ 1;
    const int*    cnts  = &g_ccnt[(o * BATCH + b) * NCELL];
    const float2* cells = &g_cell[(size_t)(o * BATCH + b) * NCELL * CAP];

    float best = 3.4e38f;
    {
        // 3x3 fast path; clamped coords may duplicate border cells (min is
        // idempotent). Counts prefetched as 9 independent loads (MLP).
        int xm = max(cx - 1, 0), xp = min(cx + 1, GDIM - 1);
        int ym = max(cy - 1, 0), yp = min(cy + 1, GDIM - 1);
        int cid[9];
        cid[0] = ym * GDIM + xm; cid[1] = ym * GDIM + cx; cid[2] = ym * GDIM + xp;
        cid[3] = cy * GDIM + xm; cid[4] = cy * GDIM + cx; cid[5] = cy * GDIM + xp;
        cid[6] = yp * GDIM + xm; cid[7] = yp * GDIM + cx; cid[8] = yp * GDIM + xp;
        int n9[9];
        #pragma unroll
        for (int j = 0; j < 9; j++) n9[j] = min(cnts[cid[j]], CAP);
        #pragma unroll
        for (int j = 0; j < 9; j++) {
            const float2* p = &cells[(size_t)cid[j] * CAP];
            for (int u = 0; u < n9[j]; u++) {
                float2 tp = p[u];
                float dx = q.x - tp.x, dy = q.y - tp.y;
                best = fminf(best, fmaf(dx, dx, dy * dy));
            }
        }
    }
    // Straggler rings (P ~ 0.2%): ring-k cells are >= (k-1)*H away.
    #pragma unroll 1
    for (int k = 2; k < GDIM; k++) {
        float rd = (float)(k - 1) * HCELL;
        if (best <= rd * rd) break;
        int y0 = max(cy - k, 0), y1 = min(cy + k, GDIM - 1);
        int x0 = max(cx - k, 0), x1 = min(cx + k, GDIM - 1);
        for (int yy = y0; yy <= y1; yy++) {
            if (yy == cy - k || yy == cy + k) {
                for (int xx = x0; xx <= x1; xx++)
                    scan_cell(cnts, cells, yy * GDIM + xx, q.x, q.y, best);
            } else {
                if (cx - k >= 0)   scan_cell(cnts, cells, yy * GDIM + cx - k, q.x, q.y, best);
                if (cx + k < GDIM) scan_cell(cnts, cells, yy * GDIM + cx + k, q.x, q.y, best);
            }
        }
    }

    // ---- Block partial (fixed order) + last-block finalization ----
    __shared__ float sm[NTHR];
    __shared__ unsigned last;
    sm[t] = best;
    __syncthreads();
    for (int off = NTHR / 2; off > 0; off >>= 1) {
        if (t < off) sm[t] += sm[t + off];
        __syncthreads();
    }
    if (t == 0) {
        g_part[bid] = sm[0];
        __threadfence();
        last = (atomicAdd(&g_done, 1u) == NBLK - 1) ? 1u : 0u;
    }
    __syncthreads();

    if (last) {
        __threadfence();
        sm[t] = ((volatile float*)g_part)[t];    // bypass L1; all writes released
        __syncthreads();
        for (int off = NTHR / 2; off > 0; off >>= 1) {
            if (t < off) sm[t] += sm[t + off];
            __syncthreads();
        }
        if (t == 0) {
            out[0] = sm[0] * (1.0f / (float)(BATCH * NPTS));
            g_done = 0;                           // reset for next replay
        }
        // Re-zero count table for the next replay (counts are dead here:
        // every block has finished searching before the last arrive).
        int4* cc = (int4*)g_ccnt;
        #pragma unroll 4
        for (int j = t; j < NTAB * NCELL / 4; j += NTHR)
            cc[j] = make_int4(0, 0, 0, 0);
    }
}

extern "C" void kernel_launch(void* const* d_in, const int* in_sizes, int n_in,
                              void* d_out, int out_size) {
    const float2* pred = (const float2*)d_in[0];
    const float2* gt   = (const float2*)d_in[1];
    chamfer_all<<<NBLK, NTHR>>>(pred, gt, (float*)d_out);
}

// round 12
// speedup vs baseline: 1.0840x; 1.0840x over previous
#include <cuda_runtime.h>
#include <cstdint>

#define BATCH 4
#define NPTS  8192
#define GDIM  64                  // grid cells per axis
#define NCELL (GDIM * GDIM)       // 4096
#define CAP   20                  // max pts/cell (lambda=2; P(overflow)~1e-14)
#define HCELL (1.0f / GDIM)
#define NTAB  (2 * BATCH)         // set s (0=pred,1=gt) x batch
#define NQ    (2 * BATCH * NPTS)  // 65536 points == queries
#define NTHR  256
#define NSB   (2 * NQ / NTHR)     // 512 search blocks (2 threads per query)

// Persistent scratch (zero at load; search's last block re-zeros counts)
__device__ int      g_ccnt[NTAB * NCELL];
__device__ float2   g_cell[NTAB * NCELL * CAP];    // 5.2 MB (L2-resident)
__device__ float    g_part[NSB];
__device__ unsigned g_done;

// ============================================================================
// K1: bin all points (atomicAdd slot; drop on overflow - P~0)
// ============================================================================
__global__ __launch_bounds__(NTHR) void k_fill(const float2* __restrict__ pred,
                                               const float2* __restrict__ gt) {
    int gid = blockIdx.x * NTHR + threadIdx.x;         // 0..65535
    int s = gid >> 15, b = (gid >> 13) & 3, i = gid & (NPTS - 1);
    const float2* src = s ? gt : pred;
    float2 p = src[b * NPTS + i];
    int cx = min(GDIM - 1, max(0, (int)(p.x * (float)GDIM)));
    int cy = min(GDIM - 1, max(0, (int)(p.y * (float)GDIM)));
    int cell = (s * BATCH + b) * NCELL + cy * GDIM + cx;
    int pos = atomicAdd(&g_ccnt[cell], 1);
    if (pos < CAP) g_cell[cell * CAP + pos] = p;
}

__device__ __forceinline__ void scan_cell(const int* __restrict__ cnts,
                                          const float2* __restrict__ cells,
                                          int c, float qx, float qy, float& best) {
    int n = min(cnts[c], CAP);
    const float2* p = &cells[(size_t)c * CAP];
    for (int j = 0; j < n; j++) {
        float2 t = p[j];
        float dx = qx - t.x, dy = qy - t.y;
        best = fminf(best, fmaf(dx, dx, dy * dy));
    }
}

// ============================================================================
// K2: exact NN, TWO threads per query (adjacent lanes; half = gid&1).
// Fast path: 3x3 neighborhood split 5/4 cells across the pair, counts
// prefetched as independent LDGs, combined with one shfl_xor(1) min.
// Stragglers (best > H^2 after 3x3; P~0.2%): even lane runs expanding
// Chebyshev rings (ring-k cells are >= (k-1)*H away -> exact termination).
// Result depends only on candidate sets -> deterministic under atomic order.
// Block partial sums in fixed order; last block (g_done) does the fixed-order
// 512-way final sum and re-zeros g_ccnt for the next graph replay.
// ============================================================================
__global__ __launch_bounds__(NTHR) void k_search(const float2* __restrict__ pred,
                                                 const float2* __restrict__ gt,
                                                 float* __restrict__ out) {
    const int t = threadIdx.x, bid = blockIdx.x;
    const int tgid = bid * NTHR + t;                   // 0..131071
    const int gid = tgid >> 1, half = tgid & 1;        // query id, half id
    const int s = gid >> 15, b = (gid >> 13) & 3, i = gid & (NPTS - 1);

    const float2* qsrc = s ? gt : pred;
    const float2 q = qsrc[b * NPTS + i];
    const int o = s ^ 1;                               // search the OTHER set
    const int*    cnts  = &g_ccnt[(o * BATCH + b) * NCELL];
    const float2* cells = &g_cell[(size_t)(o * BATCH + b) * NCELL * CAP];

    const int cx = min(GDIM - 1, max(0, (int)(q.x * (float)GDIM)));
    const int cy = min(GDIM - 1, max(0, (int)(q.y * (float)GDIM)));

    float best = 3.4e38f;
    {
        // 3x3 cell ids (clamped; duplicates OK - min is idempotent)
        int xm = max(cx - 1, 0), xp = min(cx + 1, GDIM - 1);
        int ym = max(cy - 1, 0), yp = min(cy + 1, GDIM - 1);
        int cid[9];
        cid[0] = ym * GDIM + xm; cid[1] = ym * GDIM + cx; cid[2] = ym * GDIM + xp;
        cid[3] = cy * GDIM + xm; cid[4] = cy * GDIM + cx; cid[5] = cy * GDIM + xp;
        cid[6] = yp * GDIM + xm; cid[7] = yp * GDIM + cx; cid[8] = yp * GDIM + xp;

        // This lane's share: half 0 -> cells 0..4, half 1 -> cells 5..8
        int base = half ? 5 : 0;
        int nc   = half ? 4 : 5;
        int myid[5], myn[5];
        #pragma unroll
        for (int j = 0; j < 5; j++) myid[j] = cid[base + ((j < nc) ? j : 0)];
        #pragma unroll
        for (int j = 0; j < 5; j++) myn[j] = min(cnts[myid[j]], CAP);   // MLP batch
        #pragma unroll
        for (int j = 0; j < 5; j++) {
            if (j >= nc) break;
            const float2* p = &cells[(size_t)myid[j] * CAP];
            for (int u = 0; u < myn[j]; u++) {
                float2 tp = p[u];
                float dx = q.x - tp.x, dy = q.y - tp.y;
                best = fminf(best, fmaf(dx, dx, dy * dy));
            }
        }
        // Combine the pair (lanes 2k,2k+1 adjacent in the warp)
        best = fminf(best, __shfl_xor_sync(0xFFFFFFFFu, best, 1));
    }

    // Straggler rings on even lane only (pair already combined)
    if (half == 0 && best > HCELL * HCELL) {
        #pragma unroll 1
        for (int k = 2; k < GDIM; k++) {
            float rd = (float)(k - 1) * HCELL;
            if (best <= rd * rd) break;
            int y0 = max(cy - k, 0), y1 = min(cy + k, GDIM - 1);
            int x0 = max(cx - k, 0), x1 = min(cx + k, GDIM - 1);
            for (int yy = y0; yy <= y1; yy++) {
                if (yy == cy - k || yy == cy + k) {
                    for (int xx = x0; xx <= x1; xx++)
                        scan_cell(cnts, cells, yy * GDIM + xx, q.x, q.y, best);
                } else {
                    if (cx - k >= 0)   scan_cell(cnts, cells, yy * GDIM + cx - k, q.x, q.y, best);
                    if (cx + k < GDIM) scan_cell(cnts, cells, yy * GDIM + cx + k, q.x, q.y, best);
                }
            }
        }
    }

    // ---- Block partial (each query counted once: even lane contributes) ----
    __shared__ float sm[NTHR];
    __shared__ unsigned lastf;
    sm[t] = (half == 0) ? best : 0.0f;
    __syncthreads();
    for (int off = NTHR / 2; off > 0; off >>= 1) {
        if (t < off) sm[t] += sm[t + off];
        __syncthreads();
    }
    if (t == 0) {
        g_part[bid] = sm[0];
        __threadfence();
        lastf = (atomicAdd(&g_done, 1u) == NSB - 1) ? 1u : 0u;
    }
    __syncthreads();

    if (lastf) {
        __threadfence();
        float a = ((volatile float*)g_part)[t] + ((volatile float*)g_part)[t + NTHR];
        sm[t] = a;
        __syncthreads();
        for (int off = NTHR / 2; off > 0; off >>= 1) {
            if (t < off) sm[t] += sm[t + off];
            __syncthreads();
        }
        if (t == 0) {
            out[0] = sm[0] * (1.0f / (float)(BATCH * NPTS));
            g_done = 0;                           // reset for next replay
        }
        // Re-zero counts for the next replay (dead by now: all searches done)
        int4* cc = (int4*)g_ccnt;
        #pragma unroll 4
        for (int j = t; j < NTAB * NCELL / 4; j += NTHR)
            cc[j] = make_int4(0, 0, 0, 0);
    }
}

extern "C" void kernel_launch(void* const* d_in, const int* in_sizes, int n_in,
                              void* d_out, int out_size) {
    const float2* pred = (const float2*)d_in[0];
    const float2* gt   = (const float2*)d_in[1];

    k_fill<<<NQ / NTHR, NTHR>>>(pred, gt);
    k_search<<<NSB, NTHR>>>(pred, gt, (float*)d_out);
}